// round 9
// baseline (speedup 1.0000x reference)
#include <cuda_runtime.h>
#include <cstdint>

// MoEAllReduce: fused expert-weighted reduction + residual add + RMSNorm.
// out[0 : T*H]     = hidden_states
// out[T*H : 2*T*H] = output_residual
//
// One CTA per token row t. 512 threads; fast path (E=8, H=4096) fully
// unrolled with both per-thread float4 chunks handled as explicit PAIRS so
// every stream contributes two independent LDG.128s back-to-back (max MLP
// at fixed register budget). __launch_bounds__(512,3) -> 1536 thr/SM
// (empirical optimum). Batched loads -> single-barrier redundant block
// reduce -> batched stores. Streaming cache hints on zero-reuse streams.

#define NTHREADS 512
#define NWARPS (NTHREADS / 32)
#define MAX_ITEMS 8

__device__ __forceinline__ float warp_reduce_sum(float v) {
#pragma unroll
    for (int off = 16; off > 0; off >>= 1)
        v += __shfl_xor_sync(0xFFFFFFFFu, v, off);
    return v;
}

// ---------------- fast path: E=8, H = 8*NTHREADS (2 float4/thread) -------
__global__ __launch_bounds__(NTHREADS, 3)
void moe_fast_kernel(
    const float* __restrict__ residual,     // [T, H]
    const float* __restrict__ norm_weight,  // [H]
    const float* __restrict__ scale,        // [E, T]
    const float* __restrict__ A,            // [E, T, H]
    const float* __restrict__ token,        // [T, H]
    float* __restrict__ hidden,             // [T, H]
    float* __restrict__ out_res,            // [T, H]
    int T, int H)
{
    const int t = blockIdx.x;
    const int tid = threadIdx.x;
    const int h4 = H >> 2;

    __shared__ float s_scale[8];
    __shared__ float s_warp[NWARPS];

    if (tid < 8) s_scale[tid] = scale[(size_t)tid * T + t];
    __syncthreads();

    const float4* __restrict__ res4 = (const float4*)(residual + (size_t)t * H);
    const float4* __restrict__ tok4 = (const float4*)(token    + (size_t)t * H);
    const float4* __restrict__ A4   = (const float4*)A;
    const size_t rowStride4 = (size_t)T * h4;
    const size_t rowBase4   = (size_t)t * h4;

    const int i0 = tid;                // chunk 0 index
    const int i1 = tid + NTHREADS;     // chunk 1 index

    // Paired loads per stream: two independent LDG.128s per dependency chain.
    float4 a0, a1;
    {
        float4 r0 = __ldcs(&res4[i0]);
        float4 r1 = __ldcs(&res4[i1]);
        float4 k0 = __ldcs(&tok4[i0]);
        float4 k1 = __ldcs(&tok4[i1]);
        a0.x = r0.x + k0.x; a0.y = r0.y + k0.y; a0.z = r0.z + k0.z; a0.w = r0.w + k0.w;
        a1.x = r1.x + k1.x; a1.y = r1.y + k1.y; a1.z = r1.z + k1.z; a1.w = r1.w + k1.w;
    }

#pragma unroll
    for (int e = 0; e < 8; e++) {
        const float se = s_scale[e];
        const size_t b = (size_t)e * rowStride4 + rowBase4;
        float4 v0 = __ldcs(&A4[b + i0]);
        float4 v1 = __ldcs(&A4[b + i1]);
        a0.x = fmaf(se, v0.x, a0.x);
        a0.y = fmaf(se, v0.y, a0.y);
        a0.z = fmaf(se, v0.z, a0.z);
        a0.w = fmaf(se, v0.w, a0.w);
        a1.x = fmaf(se, v1.x, a1.x);
        a1.y = fmaf(se, v1.y, a1.y);
        a1.z = fmaf(se, v1.z, a1.z);
        a1.w = fmaf(se, v1.w, a1.w);
    }

    float ss = a0.x * a0.x + a0.y * a0.y + a0.z * a0.z + a0.w * a0.w
             + a1.x * a1.x + a1.y * a1.y + a1.z * a1.z + a1.w * a1.w;

    // Single-barrier redundant block reduction (no warp-0 serialization).
    ss = warp_reduce_sum(ss);
    const int wid = tid >> 5;
    const int lid = tid & 31;
    if (lid == 0) s_warp[wid] = ss;
    __syncthreads();
    float v = (lid < NWARPS) ? s_warp[lid] : 0.0f;
    v = warp_reduce_sum(v);
    const float inv = rsqrtf(v / (float)H + 1e-5f);

    const float4* __restrict__ w4 = (const float4*)norm_weight;
    float4* __restrict__ o_res4 = (float4*)(out_res + (size_t)t * H);
    float4* __restrict__ o_hid4 = (float4*)(hidden  + (size_t)t * H);

    float4 w0 = __ldg(&w4[i0]);
    float4 w1 = __ldg(&w4[i1]);

    float4 h0, h1;
    h0.x = a0.x * inv * w0.x; h0.y = a0.y * inv * w0.y;
    h0.z = a0.z * inv * w0.z; h0.w = a0.w * inv * w0.w;
    h1.x = a1.x * inv * w1.x; h1.y = a1.y * inv * w1.y;
    h1.z = a1.z * inv * w1.z; h1.w = a1.w * inv * w1.w;

    __stcs(&o_res4[i0], a0);
    __stcs(&o_res4[i1], a1);
    __stcs(&o_hid4[i0], h0);
    __stcs(&o_hid4[i1], h1);
}

// ---------------- generic fallback (float4, proven R5 structure) ---------
__global__ __launch_bounds__(NTHREADS, 3)
void moe_generic_kernel(
    const float* __restrict__ residual,
    const float* __restrict__ norm_weight,
    const float* __restrict__ scale,
    const float* __restrict__ A,
    const float* __restrict__ token,
    float* __restrict__ hidden,
    float* __restrict__ out_res,
    int E, int T, int H)
{
    const int t = blockIdx.x;
    const int tid = threadIdx.x;
    const int h4 = H >> 2;
    const int items = h4 / NTHREADS;

    __shared__ float s_scale[32];
    __shared__ float s_warp[NWARPS];

    if (tid < E) s_scale[tid] = scale[(size_t)tid * T + t];
    __syncthreads();

    const float4* __restrict__ res4 = (const float4*)(residual + (size_t)t * H);
    const float4* __restrict__ tok4 = (const float4*)(token    + (size_t)t * H);
    const float4* __restrict__ A4   = (const float4*)A;
    const size_t rowStride4 = (size_t)T * h4;
    const size_t rowBase4   = (size_t)t * h4;

    float4 acc[MAX_ITEMS];
    float ss = 0.0f;

#pragma unroll
    for (int i = 0; i < MAX_ITEMS; i++) {
        if (i >= items) break;
        const int idx = tid + i * NTHREADS;
        float4 r = __ldcs(&res4[idx]);
        float4 k = __ldcs(&tok4[idx]);
        float4 a;
        a.x = r.x + k.x; a.y = r.y + k.y; a.z = r.z + k.z; a.w = r.w + k.w;
        for (int e = 0; e < E; e++) {
            const float se = s_scale[e];
            float4 v = __ldcs(&A4[(size_t)e * rowStride4 + rowBase4 + idx]);
            a.x = fmaf(se, v.x, a.x);
            a.y = fmaf(se, v.y, a.y);
            a.z = fmaf(se, v.z, a.z);
            a.w = fmaf(se, v.w, a.w);
        }
        acc[i] = a;
        ss += a.x * a.x + a.y * a.y + a.z * a.z + a.w * a.w;
    }

    ss = warp_reduce_sum(ss);
    const int wid = tid >> 5;
    const int lid = tid & 31;
    if (lid == 0) s_warp[wid] = ss;
    __syncthreads();
    float v = (lid < NWARPS) ? s_warp[lid] : 0.0f;
    v = warp_reduce_sum(v);
    const float inv = rsqrtf(v / (float)H + 1e-5f);

    const float4* __restrict__ w4 = (const float4*)norm_weight;
    float4* __restrict__ o_res4 = (float4*)(out_res + (size_t)t * H);
    float4* __restrict__ o_hid4 = (float4*)(hidden  + (size_t)t * H);

#pragma unroll
    for (int i = 0; i < MAX_ITEMS; i++) {
        if (i >= items) break;
        const int idx = tid + i * NTHREADS;
        float4 a = acc[i];
        float4 w = __ldg(&w4[idx]);
        float4 hOut;
        hOut.x = a.x * inv * w.x;
        hOut.y = a.y * inv * w.y;
        hOut.z = a.z * inv * w.z;
        hOut.w = a.w * inv * w.w;
        __stcs(&o_res4[idx], a);
        __stcs(&o_hid4[idx], hOut);
    }
}

extern "C" void kernel_launch(void* const* d_in, const int* in_sizes, int n_in,
                              void* d_out, int out_size)
{
    const float* residual = (const float*)d_in[0];   // [T, H]
    const float* weight   = (const float*)d_in[1];   // [H]
    const float* scale    = (const float*)d_in[2];   // [E, T]
    const float* A        = (const float*)d_in[3];   // [E, T, H]
    const float* token    = (const float*)d_in[4];   // [T, H]

    const int H = in_sizes[1];
    const int TH = in_sizes[0];
    const int T = TH / H;
    const int E = in_sizes[2] / T;

    float* hidden  = (float*)d_out;              // [T, H]
    float* out_res = (float*)d_out + (size_t)TH; // [T, H]

    dim3 grid(T);
    dim3 block(NTHREADS);
    if (E == 8 && H == 8 * NTHREADS) {
        moe_fast_kernel<<<grid, block>>>(
            residual, weight, scale, A, token, hidden, out_res, T, H);
    } else {
        moe_generic_kernel<<<grid, block>>>(
            residual, weight, scale, A, token, hidden, out_res, E, T, H);
    }
}